// round 9
// baseline (speedup 1.0000x reference)
#include <cuda_runtime.h>

#define IN_DIM   8192
#define OUT_DIM  16384
#define TOPK     327
#define NBINS    9216            // 768 threads * 12 bins >= 8193
#define NTILES   16              // column tiles of 1024
#define NSPLITS  32              // row splits of 256
#define ROWS_PER_SPLIT 256

// ---------------- device scratch (no allocations allowed) ----------------
__device__ int g_overlap[OUT_DIM];
__device__ int g_active[IN_DIM];
__device__ int g_nactive;
__device__ int g_hist[NBINS];
__device__ int g_tilecnt[NTILES];
__device__ int g_T;
__device__ int g_nat;
__device__ int g_tie[OUT_DIM];
__device__ int g_ntie;

// ---------------- kernel 1: zero scratch ----------------
__global__ void k_init() {
    int i = blockIdx.x * blockDim.x + threadIdx.x;   // grid 16 x 1024 = 16384
    if (i < OUT_DIM) g_overlap[i] = 0;
    if (i < NBINS)   g_hist[i] = 0;
    if (i < NTILES)  g_tilecnt[i] = 0;
    if (i == 0) { g_nactive = 0; g_ntie = 0; }
}

// ---------------- kernel 2: compact active rows (multi-block, int4) ------
__global__ void k_compact(const int* __restrict__ x) {
    int i = (blockIdx.x * blockDim.x + threadIdx.x) * 4;   // grid 8 x 256
    int4 v = *reinterpret_cast<const int4*>(x + i);
    // ptxas warp-aggregates uniform-address atomicAdd; order is arbitrary but
    // the GEMV sum over rows is order-invariant in int32.
    if (v.x) { int p = atomicAdd(&g_nactive, 1); g_active[p] = i + 0; }
    if (v.y) { int p = atomicAdd(&g_nactive, 1); g_active[p] = i + 1; }
    if (v.z) { int p = atomicAdd(&g_nactive, 1); g_active[p] = i + 2; }
    if (v.w) { int p = atomicAdd(&g_nactive, 1); g_active[p] = i + 3; }
}

// ---------------- kernel 3: binarized GEMV + fused histogram -------------
// grid (NTILES, NSPLITS), 256 threads, 4 cols/thread via float4.
// The last-finishing block of each column tile builds the histogram for its
// 1024 finalized overlap values.
__global__ void __launch_bounds__(256) k_gemv(const float* __restrict__ p) {
    __shared__ int srows[ROWS_PER_SPLIT];
    __shared__ int s_last;
    int t = threadIdx.x;
    int na = g_nactive;
    int base = blockIdx.y * ROWS_PER_SPLIT;
    int cnt = na - base;
    if (cnt > ROWS_PER_SPLIT) cnt = ROWS_PER_SPLIT;

    int col = blockIdx.x * 1024 + t * 4;

    if (cnt > 0) {
        if (t < cnt) srows[t] = g_active[base + t];
        __syncthreads();

        int a0 = 0, a1 = 0, a2 = 0, a3 = 0;
        #pragma unroll 4
        for (int r = 0; r < cnt; r++) {
            int row = srows[r];
            const float4 v = __ldg(reinterpret_cast<const float4*>(
                p + (size_t)row * OUT_DIM + col));
            // jnp.round is half-to-even: round(0.5)=0 -> connection = (p > 0.5)
            a0 += (v.x > 0.5f);
            a1 += (v.y > 0.5f);
            a2 += (v.z > 0.5f);
            a3 += (v.w > 0.5f);
        }
        atomicAdd(&g_overlap[col + 0], a0);
        atomicAdd(&g_overlap[col + 1], a1);
        atomicAdd(&g_overlap[col + 2], a2);
        atomicAdd(&g_overlap[col + 3], a3);
    }

    // tile completion: last block per column tile builds histogram
    __threadfence();
    __syncthreads();
    if (t == 0) s_last = atomicAdd(&g_tilecnt[blockIdx.x], 1);
    __syncthreads();
    if (s_last == NSPLITS - 1) {
        const int4 ov = *reinterpret_cast<const int4*>(&g_overlap[col]);
        atomicAdd(&g_hist[ov.x], 1);
        atomicAdd(&g_hist[ov.y], 1);
        atomicAdd(&g_hist[ov.z], 1);
        atomicAdd(&g_hist[ov.w], 1);
    }
}

// ---------------- kernel 4: find threshold T + tie budget ----------------
// 1 block, 1024 threads; threads 0..767 own 12 bins each (3x int4).
__global__ void __launch_bounds__(1024) k_findT() {
    __shared__ int scan[1024];
    int t = threadIdx.x;

    int v[12];
    int lsum = 0;
    if (t < 768) {
        const int4* h4 = reinterpret_cast<const int4*>(g_hist);
        int b = t * 3;
        int4 a = h4[b], bq = h4[b + 1], c = h4[b + 2];
        v[0]=a.x; v[1]=a.y; v[2]=a.z;  v[3]=a.w;
        v[4]=bq.x;v[5]=bq.y;v[6]=bq.z; v[7]=bq.w;
        v[8]=c.x; v[9]=c.y; v[10]=c.z; v[11]=c.w;
        #pragma unroll
        for (int j = 0; j < 12; j++) lsum += v[j];
    }
    scan[t] = lsum;
    __syncthreads();
    for (int off = 1; off < 1024; off <<= 1) {
        int s = (t >= off) ? scan[t - off] : 0;
        __syncthreads();
        scan[t] += s;
        __syncthreads();
    }
    int prefix = (t == 0) ? 0 : scan[t - 1];

    const int CUT = OUT_DIM - TOPK;  // 16057
    if (t < 768) {
        int run = prefix;
        int b0 = t * 12;
        #pragma unroll
        for (int j = 0; j < 12; j++) {
            int h = v[j];
            if (run <= CUT && run + h > CUT) {
                g_T   = b0 + j;
                g_nat = TOPK - (OUT_DIM - (run + h));  // ties to take (lowest idx)
            }
            run += h;
        }
    }
}

// ---------------- kernel 5: bulk output write + tie collection -----------
// grid 16 x 256, int4 in / float4 out.
__global__ void __launch_bounds__(256) k_out(float* __restrict__ out) {
    int i = (blockIdx.x * blockDim.x + threadIdx.x) * 4;
    const int T = g_T;
    const int4 ov = *reinterpret_cast<const int4*>(&g_overlap[i]);
    float4 f;
    f.x = (ov.x > T) ? 1.0f : 0.0f;
    f.y = (ov.y > T) ? 1.0f : 0.0f;
    f.z = (ov.z > T) ? 1.0f : 0.0f;
    f.w = (ov.w > T) ? 1.0f : 0.0f;
    *reinterpret_cast<float4*>(out + i) = f;
    if (ov.x == T) { int p = atomicAdd(&g_ntie, 1); g_tie[p] = i + 0; }
    if (ov.y == T) { int p = atomicAdd(&g_ntie, 1); g_tie[p] = i + 1; }
    if (ov.z == T) { int p = atomicAdd(&g_ntie, 1); g_tie[p] = i + 2; }
    if (ov.w == T) { int p = atomicAdd(&g_ntie, 1); g_tie[p] = i + 3; }
}

// ---------------- kernel 6: resolve ties (lowest-index wins) -------------
// 1 block, 256 threads. n is typically tiny (tens); rank by counting
// smaller indices — exact jax.lax.top_k stable tie-break.
__global__ void __launch_bounds__(256) k_ties(float* __restrict__ out) {
    int t = threadIdx.x;
    int n = g_ntie;
    int nat = g_nat;
    for (int k = t; k < n; k += 256) {
        int idx = g_tie[k];
        int rank = 0;
        for (int j = 0; j < n; j++) rank += (g_tie[j] < idx);
        if (rank < nat) out[idx] = 1.0f;
    }
}

// ---------------- launch ----------------
extern "C" void kernel_launch(void* const* d_in, const int* in_sizes, int n_in,
                              void* d_out, int out_size) {
    const int*   x;
    const float* p;
    if (in_sizes[0] == IN_DIM) {
        x = (const int*)d_in[0];
        p = (const float*)d_in[1];
    } else {
        x = (const int*)d_in[1];
        p = (const float*)d_in[0];
    }

    k_init<<<16, 1024>>>();
    k_compact<<<8, 256>>>(x);
    k_gemv<<<dim3(NTILES, NSPLITS), 256>>>(p);
    k_findT<<<1, 1024>>>();
    k_out<<<16, 256>>>((float*)d_out);
    k_ties<<<1, 256>>>((float*)d_out);
}

// round 10
// speedup vs baseline: 1.0250x; 1.0250x over previous
#include <cuda_runtime.h>

#define IN_DIM   8192
#define OUT_DIM  16384
#define TOPK     327
#define NBINS    9216            // 256 threads * 36 bins >= 8193
#define NTILES   16              // column tiles of 1024
#define NSPLITS  32              // row splits of 256
#define ROWS_PER_SPLIT 256
#define CUT      (OUT_DIM - TOPK)   // 16057

// ---------------- device scratch (no allocations allowed) ----------------
__device__ int g_overlap[OUT_DIM];
__device__ int g_active[IN_DIM];
__device__ int g_nactive;
__device__ int g_hist[NBINS];
__device__ int g_tilecnt[NTILES];
__device__ int g_donecnt;
__device__ int g_tie[OUT_DIM];
__device__ int g_ntie;

// ================= kernel 1: zero scratch + ordered compact ==============
// Single block, 1024 threads. Zeroing is int4 stores; compaction uses a
// block-wide scan so g_active is index-ordered and g_nactive is exact.
__global__ void __launch_bounds__(1024) k_prep(const int* __restrict__ x) {
    __shared__ int warp_sums[32];
    int t = threadIdx.x;
    int lane = t & 31, w = t >> 5;

    // zero overlap (4096 int4), hist (2304 int4), counters
    int4 z4 = make_int4(0, 0, 0, 0);
    int4* ov4 = reinterpret_cast<int4*>(g_overlap);
    for (int i = t; i < OUT_DIM / 4; i += 1024) ov4[i] = z4;
    int4* h4 = reinterpret_cast<int4*>(g_hist);
    for (int i = t; i < NBINS / 4; i += 1024) h4[i] = z4;
    if (t < NTILES) g_tilecnt[t] = 0;
    if (t == 0) { g_donecnt = 0; g_ntie = 0; }

    // compact: each thread owns 8 contiguous x values (2 int4)
    const int4* x4 = reinterpret_cast<const int4*>(x);
    int4 a = x4[t * 2], b = x4[t * 2 + 1];
    int vals[8] = {a.x, a.y, a.z, a.w, b.x, b.y, b.z, b.w};
    int cnt = 0;
    #pragma unroll
    for (int j = 0; j < 8; j++) cnt += (vals[j] != 0);

    // block inclusive scan of cnt
    int incl = cnt;
    #pragma unroll
    for (int o = 1; o < 32; o <<= 1) {
        int s = __shfl_up_sync(0xffffffffu, incl, o);
        if (lane >= o) incl += s;
    }
    if (lane == 31) warp_sums[w] = incl;
    __syncthreads();
    if (w == 0) {
        int ws = warp_sums[lane];
        int wincl = ws;
        #pragma unroll
        for (int o = 1; o < 32; o <<= 1) {
            int s = __shfl_up_sync(0xffffffffu, wincl, o);
            if (lane >= o) wincl += s;
        }
        warp_sums[lane] = wincl - ws;   // exclusive warp offsets
    }
    __syncthreads();
    int pos = incl - cnt + warp_sums[w];   // exclusive prefix for this thread
    int base_i = t * 8;
    #pragma unroll
    for (int j = 0; j < 8; j++)
        if (vals[j]) g_active[pos++] = base_i + j;
    if (t == 1023) g_nactive = pos;
}

// ================= kernel 2: binarized GEMV + fused histogram ============
__global__ void __launch_bounds__(256) k_gemv(const float* __restrict__ p) {
    __shared__ int srows[ROWS_PER_SPLIT];
    __shared__ int s_last;
    int t = threadIdx.x;
    int na = g_nactive;
    int base = blockIdx.y * ROWS_PER_SPLIT;
    int cnt = na - base;
    if (cnt > ROWS_PER_SPLIT) cnt = ROWS_PER_SPLIT;

    int col = blockIdx.x * 1024 + t * 4;

    if (cnt > 0) {
        if (t < cnt) srows[t] = g_active[base + t];
        __syncthreads();

        int a0 = 0, a1 = 0, a2 = 0, a3 = 0;
        #pragma unroll 4
        for (int r = 0; r < cnt; r++) {
            int row = srows[r];
            const float4 v = __ldg(reinterpret_cast<const float4*>(
                p + (size_t)row * OUT_DIM + col));
            // jnp.round is half-to-even: round(0.5)=0 -> connection = (p > 0.5)
            a0 += (v.x > 0.5f);
            a1 += (v.y > 0.5f);
            a2 += (v.z > 0.5f);
            a3 += (v.w > 0.5f);
        }
        atomicAdd(&g_overlap[col + 0], a0);
        atomicAdd(&g_overlap[col + 1], a1);
        atomicAdd(&g_overlap[col + 2], a2);
        atomicAdd(&g_overlap[col + 3], a3);
    }

    // tile completion: last block per column tile histograms its 1024 overlaps
    __threadfence();
    __syncthreads();
    if (t == 0) s_last = atomicAdd(&g_tilecnt[blockIdx.x], 1);
    __syncthreads();
    if (s_last == NSPLITS - 1) {
        __threadfence();   // acquire side: make peer atomics visible
        const int4 ov = *reinterpret_cast<const int4*>(&g_overlap[col]);
        atomicAdd(&g_hist[ov.x], 1);
        atomicAdd(&g_hist[ov.y], 1);
        atomicAdd(&g_hist[ov.z], 1);
        atomicAdd(&g_hist[ov.w], 1);
    }
}

// ================= kernel 3: findT (per-block) + write + tie resolve =====
// grid 16 x 256. Each block redundantly scans the 9216-bin histogram (L2
// resident) to find threshold T and tie budget, then writes its 1024-column
// slice. The last-finishing block resolves ties (lowest index wins — exact
// jax.lax.top_k stability).
__global__ void __launch_bounds__(256) k_out(float* __restrict__ out) {
    __shared__ int warp_sums[8];
    __shared__ int sT, sNat, s_last;
    int t = threadIdx.x;
    int lane = t & 31, w = t >> 5;

    // --- load my 36 bins (9 int4) and sum ---
    int v[36];
    {
        const int4* h4 = reinterpret_cast<const int4*>(g_hist);
        int b = t * 9;
        #pragma unroll
        for (int q = 0; q < 9; q++) {
            int4 hv = h4[b + q];
            v[q * 4 + 0] = hv.x; v[q * 4 + 1] = hv.y;
            v[q * 4 + 2] = hv.z; v[q * 4 + 3] = hv.w;
        }
    }
    int lsum = 0;
    #pragma unroll
    for (int j = 0; j < 36; j++) lsum += v[j];

    // --- block scan (256 threads = 8 warps) ---
    int incl = lsum;
    #pragma unroll
    for (int o = 1; o < 32; o <<= 1) {
        int s = __shfl_up_sync(0xffffffffu, incl, o);
        if (lane >= o) incl += s;
    }
    if (lane == 31) warp_sums[w] = incl;
    __syncthreads();
    if (w == 0 && lane < 8) {
        int ws = warp_sums[lane];
        int wincl = ws;
        #pragma unroll
        for (int o = 1; o < 8; o <<= 1) {
            int s = __shfl_up_sync(0x000000ffu, wincl, o);
            if (lane >= o) wincl += s;
        }
        warp_sums[lane] = wincl - ws;
    }
    __syncthreads();
    int run = incl - lsum + warp_sums[w];   // exclusive prefix

    // --- find crossing bin ---
    {
        int b0 = t * 36;
        #pragma unroll
        for (int j = 0; j < 36; j++) {
            int h = v[j];
            if (run <= CUT && run + h > CUT) {
                sT   = b0 + j;
                sNat = TOPK - (OUT_DIM - (run + h));  // ties to take
            }
            run += h;
        }
    }
    __syncthreads();
    const int T = sT;
    const int nat = sNat;

    // --- write my 4 columns, collect ties ---
    int i = blockIdx.x * 1024 + t * 4;
    const int4 ov = *reinterpret_cast<const int4*>(&g_overlap[i]);
    float4 f;
    f.x = (ov.x > T) ? 1.0f : 0.0f;
    f.y = (ov.y > T) ? 1.0f : 0.0f;
    f.z = (ov.z > T) ? 1.0f : 0.0f;
    f.w = (ov.w > T) ? 1.0f : 0.0f;
    *reinterpret_cast<float4*>(out + i) = f;
    if (ov.x == T) { int p = atomicAdd(&g_ntie, 1); g_tie[p] = i + 0; }
    if (ov.y == T) { int p = atomicAdd(&g_ntie, 1); g_tie[p] = i + 1; }
    if (ov.z == T) { int p = atomicAdd(&g_ntie, 1); g_tie[p] = i + 2; }
    if (ov.w == T) { int p = atomicAdd(&g_ntie, 1); g_tie[p] = i + 3; }

    // --- last block resolves ties ---
    __threadfence();
    __syncthreads();
    if (t == 0) s_last = atomicAdd(&g_donecnt, 1);
    __syncthreads();
    if (s_last == NTILES - 1) {
        __threadfence();   // acquire: see all blocks' g_tie writes
        int n = *(volatile int*)&g_ntie;
        for (int k = t; k < n; k += 256) {
            int idx = g_tie[k];
            int rank = 0;
            for (int j = 0; j < n; j++) rank += (g_tie[j] < idx);
            if (rank < nat) out[idx] = 1.0f;
        }
    }
}

// ---------------- launch ----------------
extern "C" void kernel_launch(void* const* d_in, const int* in_sizes, int n_in,
                              void* d_out, int out_size) {
    const int*   x;
    const float* p;
    if (in_sizes[0] == IN_DIM) {
        x = (const int*)d_in[0];
        p = (const float*)d_in[1];
    } else {
        x = (const int*)d_in[1];
        p = (const float*)d_in[0];
    }

    k_prep<<<1, 1024>>>(x);
    k_gemv<<<dim3(NTILES, NSPLITS), 256>>>(p);
    k_out<<<NTILES, 256>>>((float*)d_out);
}

// round 11
// speedup vs baseline: 1.1659x; 1.1375x over previous
#include <cuda_runtime.h>

#define IN_DIM   8192
#define OUT_DIM  16384
#define TOPK     327
#define NBINS    9216            // 256 threads * 36 bins >= 8193
#define NTILES   16              // column tiles of 1024
#define NSPLITS  32              // row splits of 256
#define ROWS_PER_SPLIT 256
#define CUT      (OUT_DIM - TOPK)   // 16057

// ------------- device scratch (loader zero-inits; kernels restore) -------
__device__ int g_overlap[OUT_DIM];
__device__ int g_hist[NBINS];
__device__ int g_tilecnt[NTILES];
__device__ int g_donecnt;
__device__ int g_tie[OUT_DIM];
__device__ int g_ntie;

// ================= kernel 1: binarized GEMV + fused histogram ============
// grid (NTILES, NSPLITS), 256 threads. Each block compacts its own 256-row
// x-slice into smem (order-free; the int sum over rows is order-invariant),
// then accumulates 4 columns/thread via float4 loads. The last-finishing
// block per column tile histograms its 1024 finalized overlap values.
__global__ void __launch_bounds__(256) k_gemv(const float* __restrict__ p,
                                              const int* __restrict__ x) {
    __shared__ int srows[ROWS_PER_SPLIT];
    __shared__ int scnt;
    __shared__ int s_last;
    int t = threadIdx.x;

    if (t == 0) scnt = 0;
    __syncthreads();

    // local compaction of this split's rows (coalesced 1KB read, L2-shared
    // across the 16 column tiles)
    int row = blockIdx.y * ROWS_PER_SPLIT + t;
    if (x[row] != 0) {
        int pos = atomicAdd(&scnt, 1);
        srows[pos] = row;
    }
    __syncthreads();
    int cnt = scnt;

    int col = blockIdx.x * 1024 + t * 4;

    if (cnt > 0) {
        int a0 = 0, a1 = 0, a2 = 0, a3 = 0;
        #pragma unroll 4
        for (int r = 0; r < cnt; r++) {
            int rw = srows[r];
            const float4 v = __ldg(reinterpret_cast<const float4*>(
                p + (size_t)rw * OUT_DIM + col));
            // jnp.round is half-to-even: round(0.5)=0 -> connection = (p > 0.5)
            a0 += (v.x > 0.5f);
            a1 += (v.y > 0.5f);
            a2 += (v.z > 0.5f);
            a3 += (v.w > 0.5f);
        }
        atomicAdd(&g_overlap[col + 0], a0);
        atomicAdd(&g_overlap[col + 1], a1);
        atomicAdd(&g_overlap[col + 2], a2);
        atomicAdd(&g_overlap[col + 3], a3);
    }

    // tile completion: last block per column tile histograms its 1024 overlaps
    __threadfence();
    __syncthreads();
    if (t == 0) s_last = atomicAdd(&g_tilecnt[blockIdx.x], 1);
    __syncthreads();
    if (s_last == NSPLITS - 1) {
        __threadfence();   // acquire side: make peer atomics visible
        const int4 ov = *reinterpret_cast<const int4*>(&g_overlap[col]);
        atomicAdd(&g_hist[ov.x], 1);
        atomicAdd(&g_hist[ov.y], 1);
        atomicAdd(&g_hist[ov.z], 1);
        atomicAdd(&g_hist[ov.w], 1);
    }
}

// ================= kernel 2: findT (per-block) + write + ties + restore ==
// grid 16 x 256. Each block redundantly computes T from the L2-resident
// histogram (shfl scan), writes its 1024-column output slice, zeroes its
// g_overlap slice for the next replay, collects ties; the last-finishing
// block resolves ties (lowest index wins — exact jax.lax.top_k stability)
// and restores hist + counters to zero.
__global__ void __launch_bounds__(256) k_out(float* __restrict__ out) {
    __shared__ int warp_sums[8];
    __shared__ int sT, sNat, s_last;
    int t = threadIdx.x;
    int lane = t & 31, w = t >> 5;

    // --- load my 36 bins (9 int4) and sum ---
    int v[36];
    {
        const int4* h4 = reinterpret_cast<const int4*>(g_hist);
        int b = t * 9;
        #pragma unroll
        for (int q = 0; q < 9; q++) {
            int4 hv = h4[b + q];
            v[q * 4 + 0] = hv.x; v[q * 4 + 1] = hv.y;
            v[q * 4 + 2] = hv.z; v[q * 4 + 3] = hv.w;
        }
    }
    int lsum = 0;
    #pragma unroll
    for (int j = 0; j < 36; j++) lsum += v[j];

    // --- block scan (8 warps, shfl) ---
    int incl = lsum;
    #pragma unroll
    for (int o = 1; o < 32; o <<= 1) {
        int s = __shfl_up_sync(0xffffffffu, incl, o);
        if (lane >= o) incl += s;
    }
    if (lane == 31) warp_sums[w] = incl;
    __syncthreads();
    if (w == 0 && lane < 8) {
        int ws = warp_sums[lane];
        int wincl = ws;
        #pragma unroll
        for (int o = 1; o < 8; o <<= 1) {
            int s = __shfl_up_sync(0x000000ffu, wincl, o);
            if (lane >= o) wincl += s;
        }
        warp_sums[lane] = wincl - ws;
    }
    __syncthreads();
    int run = incl - lsum + warp_sums[w];   // exclusive prefix

    // --- find crossing bin ---
    {
        int b0 = t * 36;
        #pragma unroll
        for (int j = 0; j < 36; j++) {
            int h = v[j];
            if (run <= CUT && run + h > CUT) {
                sT   = b0 + j;
                sNat = TOPK - (OUT_DIM - (run + h));  // ties to take
            }
            run += h;
        }
    }
    __syncthreads();
    const int T = sT;
    const int nat = sNat;

    // --- write my 4 columns, zero my overlap slice, collect ties ---
    int i = blockIdx.x * 1024 + t * 4;
    const int4 ov = *reinterpret_cast<const int4*>(&g_overlap[i]);
    *reinterpret_cast<int4*>(&g_overlap[i]) = make_int4(0, 0, 0, 0);
    float4 f;
    f.x = (ov.x > T) ? 1.0f : 0.0f;
    f.y = (ov.y > T) ? 1.0f : 0.0f;
    f.z = (ov.z > T) ? 1.0f : 0.0f;
    f.w = (ov.w > T) ? 1.0f : 0.0f;
    *reinterpret_cast<float4*>(out + i) = f;
    if (ov.x == T) { int q = atomicAdd(&g_ntie, 1); g_tie[q] = i + 0; }
    if (ov.y == T) { int q = atomicAdd(&g_ntie, 1); g_tie[q] = i + 1; }
    if (ov.z == T) { int q = atomicAdd(&g_ntie, 1); g_tie[q] = i + 2; }
    if (ov.w == T) { int q = atomicAdd(&g_ntie, 1); g_tie[q] = i + 3; }

    // --- last block: resolve ties, then restore scratch for next replay ---
    __threadfence();
    __syncthreads();
    if (t == 0) s_last = atomicAdd(&g_donecnt, 1);
    __syncthreads();
    if (s_last == NTILES - 1) {
        __threadfence();   // acquire: see all blocks' g_tie writes
        int n = *(volatile int*)&g_ntie;
        for (int k = t; k < n; k += 256) {
            int idx = g_tie[k];
            int rank = 0;
            for (int j = 0; j < n; j++) rank += (g_tie[j] < idx);
            if (rank < nat) out[idx] = 1.0f;
        }
        // restore for next graph replay (loader guarantees zeros on call 0)
        int4* h4 = reinterpret_cast<int4*>(g_hist);
        for (int q = t; q < NBINS / 4; q += 256)
            h4[q] = make_int4(0, 0, 0, 0);
        if (t < NTILES) g_tilecnt[t] = 0;
        if (t == 0) { g_donecnt = 0; g_ntie = 0; }
    }
}

// ---------------- launch ----------------
extern "C" void kernel_launch(void* const* d_in, const int* in_sizes, int n_in,
                              void* d_out, int out_size) {
    const int*   x;
    const float* p;
    if (in_sizes[0] == IN_DIM) {
        x = (const int*)d_in[0];
        p = (const float*)d_in[1];
    } else {
        x = (const int*)d_in[1];
        p = (const float*)d_in[0];
    }

    k_gemv<<<dim3(NTILES, NSPLITS), 256>>>(p, x);
    k_out<<<NTILES, 256>>>((float*)d_out);
}

// round 15
// speedup vs baseline: 1.2869x; 1.1038x over previous
#include <cuda_runtime.h>

#define IN_DIM   8192
#define OUT_DIM  16384
#define TOPK     327
#define NBINS    9216            // 256 threads * 36 bins >= 8193
#define NTILES   16              // column tiles of 1024
#define NSPLITS  32              // row splits of 256
#define ROWS_PER_SPLIT 256
#define CUT      (OUT_DIM - TOPK)   // 16057

// ------------- device scratch (loader zero-inits; kernel restores) -------
__device__ int g_overlap[OUT_DIM];
__device__ int g_hist[NBINS];
__device__ int g_tilecnt[NTILES];
__device__ int g_histdone;       // tiles whose histogram is complete
__device__ int g_donecnt;        // tiles whose output is written
__device__ int g_tie[OUT_DIM];
__device__ int g_ntie;

// ============ single fused kernel: GEMV + hist + topk + output ===========
// grid (NTILES, NSPLITS), 256 threads/block. All 512 CTAs are co-resident
// (148 SMs, 256 thr / 48 regs / 1KB smem), so the inter-block spin barrier
// below cannot deadlock.
// Phase 1 (all 512 blocks): compact own 256-row x slice to smem, accumulate
//   4 cols/thread via float4 loads, atomicAdd into g_overlap.
// Phase 2 (16 tile-last blocks): histogram own 1024 finalized overlaps,
//   arrive on g_histdone, spin until all 16 tiles are in.
// Phase 3 (those 16 blocks): redundantly compute threshold T + tie budget
//   from the L2-resident histogram (shfl block scan), write own 1024-col
//   output slice, zero-restore own overlap slice, collect ties.
// Phase 4 (globally last block): resolve ties (lowest index wins — exact
//   jax.lax.top_k stability) and restore hist + counters for next replay.
__global__ void __launch_bounds__(256) k_fused(const float* __restrict__ p,
                                               const int* __restrict__ x,
                                               float* __restrict__ out) {
    __shared__ int srows[ROWS_PER_SPLIT];
    __shared__ int scnt;
    __shared__ int s_last;
    __shared__ int warp_sums[8];
    __shared__ int sT, sNat;
    int t = threadIdx.x;
    int lane = t & 31, w = t >> 5;

    if (t == 0) scnt = 0;
    __syncthreads();

    // ---- phase 1: local row compaction + GEMV ----
    int row = blockIdx.y * ROWS_PER_SPLIT + t;
    if (x[row] != 0) {
        int pos = atomicAdd(&scnt, 1);
        srows[pos] = row;
    }
    __syncthreads();
    int cnt = scnt;

    int col = blockIdx.x * 1024 + t * 4;

    if (cnt > 0) {
        int a0 = 0, a1 = 0, a2 = 0, a3 = 0;
        #pragma unroll 8
        for (int r = 0; r < cnt; r++) {
            int rw = srows[r];
            const float4 v = __ldg(reinterpret_cast<const float4*>(
                p + (size_t)rw * OUT_DIM + col));
            // jnp.round is half-to-even: round(0.5)=0 -> connection = (p > 0.5)
            a0 += (v.x > 0.5f);
            a1 += (v.y > 0.5f);
            a2 += (v.z > 0.5f);
            a3 += (v.w > 0.5f);
        }
        atomicAdd(&g_overlap[col + 0], a0);
        atomicAdd(&g_overlap[col + 1], a1);
        atomicAdd(&g_overlap[col + 2], a2);
        atomicAdd(&g_overlap[col + 3], a3);
    }

    // ---- tile completion ----
    __threadfence();
    __syncthreads();
    if (t == 0) s_last = atomicAdd(&g_tilecnt[blockIdx.x], 1);
    __syncthreads();
    if (s_last != NSPLITS - 1) return;   // 31 of 32 blocks per tile exit here

    // ---- phase 2: histogram own finalized overlaps ----
    __threadfence();   // acquire: peer blocks' overlap atomics visible
    const int4 ov = *reinterpret_cast<const int4*>(&g_overlap[col]);
    atomicAdd(&g_hist[ov.x], 1);
    atomicAdd(&g_hist[ov.y], 1);
    atomicAdd(&g_hist[ov.z], 1);
    atomicAdd(&g_hist[ov.w], 1);

    // global barrier among the 16 surviving blocks (deadlock-free: all CTAs
    // co-resident; spinners occupy only 16 SMs)
    __threadfence();
    __syncthreads();
    if (t == 0) {
        atomicAdd(&g_histdone, 1);
        while (atomicAdd(&g_histdone, 0) < NTILES) __nanosleep(100);
    }
    __syncthreads();
    __threadfence();   // acquire: all tiles' hist atomics visible

    // ---- phase 3a: redundant findT (36 bins/thread, shfl block scan) ----
    int v[36];
    {
        const int4* h4 = reinterpret_cast<const int4*>(g_hist);
        int b = t * 9;
        #pragma unroll
        for (int q = 0; q < 9; q++) {
            int4 hv = h4[b + q];
            v[q * 4 + 0] = hv.x; v[q * 4 + 1] = hv.y;
            v[q * 4 + 2] = hv.z; v[q * 4 + 3] = hv.w;
        }
    }
    int lsum = 0;
    #pragma unroll
    for (int j = 0; j < 36; j++) lsum += v[j];

    int incl = lsum;
    #pragma unroll
    for (int o = 1; o < 32; o <<= 1) {
        int s = __shfl_up_sync(0xffffffffu, incl, o);
        if (lane >= o) incl += s;
    }
    if (lane == 31) warp_sums[w] = incl;
    __syncthreads();
    if (w == 0 && lane < 8) {
        int ws = warp_sums[lane];
        int wincl = ws;
        #pragma unroll
        for (int o = 1; o < 8; o <<= 1) {
            int s = __shfl_up_sync(0x000000ffu, wincl, o);
            if (lane >= o) wincl += s;
        }
        warp_sums[lane] = wincl - ws;
    }
    __syncthreads();
    int run = incl - lsum + warp_sums[w];   // exclusive prefix

    {
        int b0 = t * 36;
        #pragma unroll
        for (int j = 0; j < 36; j++) {
            int h = v[j];
            if (run <= CUT && run + h > CUT) {
                sT   = b0 + j;
                sNat = TOPK - (OUT_DIM - (run + h));  // ties to take
            }
            run += h;
        }
    }
    __syncthreads();
    const int T = sT;
    const int nat = sNat;

    // ---- phase 3b: write output slice, restore overlap, collect ties ----
    *reinterpret_cast<int4*>(&g_overlap[col]) = make_int4(0, 0, 0, 0);
    float4 f;
    f.x = (ov.x > T) ? 1.0f : 0.0f;
    f.y = (ov.y > T) ? 1.0f : 0.0f;
    f.z = (ov.z > T) ? 1.0f : 0.0f;
    f.w = (ov.w > T) ? 1.0f : 0.0f;
    *reinterpret_cast<float4*>(out + col) = f;
    if (ov.x == T) { int q = atomicAdd(&g_ntie, 1); g_tie[q] = col + 0; }
    if (ov.y == T) { int q = atomicAdd(&g_ntie, 1); g_tie[q] = col + 1; }
    if (ov.z == T) { int q = atomicAdd(&g_ntie, 1); g_tie[q] = col + 2; }
    if (ov.w == T) { int q = atomicAdd(&g_ntie, 1); g_tie[q] = col + 3; }

    // ---- phase 4: globally last block resolves ties + restores scratch ----
    __threadfence();
    __syncthreads();
    if (t == 0) s_last = atomicAdd(&g_donecnt, 1);
    __syncthreads();
    if (s_last == NTILES - 1) {
        __threadfence();   // acquire: all blocks' g_tie writes visible
        int n = atomicAdd(&g_ntie, 0);
        for (int k = t; k < n; k += 256) {
            int idx = g_tie[k];
            int rank = 0;
            for (int j = 0; j < n; j++) rank += (g_tie[j] < idx);
            if (rank < nat) out[idx] = 1.0f;
        }
        // restore for next graph replay (loader guarantees zeros on call 0)
        int4* h4 = reinterpret_cast<int4*>(g_hist);
        for (int q = t; q < NBINS / 4; q += 256)
            h4[q] = make_int4(0, 0, 0, 0);
        if (t < NTILES) g_tilecnt[t] = 0;
        if (t == 0) { g_histdone = 0; g_donecnt = 0; g_ntie = 0; }
    }
}

// ---------------- launch ----------------
extern "C" void kernel_launch(void* const* d_in, const int* in_sizes, int n_in,
                              void* d_out, int out_size) {
    const int*   x;
    const float* p;
    if (in_sizes[0] == IN_DIM) {
        x = (const int*)d_in[0];
        p = (const float*)d_in[1];
    } else {
        x = (const int*)d_in[1];
        p = (const float*)d_in[0];
    }

    k_fused<<<dim3(NTILES, NSPLITS), 256>>>(p, x, (float*)d_out);
}

// round 16
// speedup vs baseline: 1.2936x; 1.0052x over previous
#include <cuda_runtime.h>

#define IN_DIM   8192
#define OUT_DIM  16384
#define TOPK     327
#define NBINS    9216            // 256 threads * 36 bins >= 8193
#define NTILES   16              // column tiles of 1024
#define NSPLITS  37              // 16 * 37 = 592 = 148 SMs * 4 CTAs (perfect balance)
#define ROWS_PER_SPLIT 222       // 37 * 222 = 8214 >= 8192 (guarded)
#define CUT      (OUT_DIM - TOPK)   // 16057

// ------------- device scratch (loader zero-inits; kernel restores) -------
__device__ int g_overlap[OUT_DIM];
__device__ int g_hist[NBINS];
__device__ int g_tilecnt[NTILES];
__device__ int g_histdone;       // tiles whose histogram is complete
__device__ int g_donecnt;        // tiles whose output is written
__device__ int g_tie[OUT_DIM];
__device__ int g_ntie;

// ============ single fused kernel: GEMV + hist + topk + output ===========
// grid (NTILES, NSPLITS) = 592 CTAs = exactly 4 per SM (one balanced wave;
// all CTAs co-resident, so the inter-block spin barrier cannot deadlock).
// Phase 1 (all 592 blocks): compact own <=222-row x slice to smem, then
//   accumulate 4 cols/thread via float4 loads, atomicAdd into g_overlap.
// Phase 2 (16 tile-last blocks): histogram own 1024 finalized overlaps,
//   arrive on g_histdone, spin until all 16 tiles are in.
// Phase 3 (those 16 blocks): redundantly compute threshold T + tie budget
//   from the L2-resident histogram (shfl block scan), write own 1024-col
//   output slice, zero-restore own overlap slice, collect ties.
// Phase 4 (globally last block): resolve ties (lowest index wins — exact
//   jax.lax.top_k stability) and restore hist + counters for next replay.
__global__ void __launch_bounds__(256, 4) k_fused(const float* __restrict__ p,
                                                  const int* __restrict__ x,
                                                  float* __restrict__ out) {
    __shared__ int srows[256];
    __shared__ int scnt;
    __shared__ int s_last;
    __shared__ int warp_sums[8];
    __shared__ int sT, sNat;
    int t = threadIdx.x;
    int lane = t & 31, w = t >> 5;

    if (t == 0) scnt = 0;
    __syncthreads();

    // ---- phase 1: local row compaction + GEMV ----
    int row = blockIdx.y * ROWS_PER_SPLIT + t;
    if (t < ROWS_PER_SPLIT && row < IN_DIM && x[row] != 0) {
        int pos = atomicAdd(&scnt, 1);
        srows[pos] = row;
    }
    __syncthreads();
    int cnt = scnt;

    int col = blockIdx.x * 1024 + t * 4;

    if (cnt > 0) {
        int a0 = 0, a1 = 0, a2 = 0, a3 = 0;
        #pragma unroll 8
        for (int r = 0; r < cnt; r++) {
            int rw = srows[r];
            const float4 v = __ldg(reinterpret_cast<const float4*>(
                p + (size_t)rw * OUT_DIM + col));
            // jnp.round is half-to-even: round(0.5)=0 -> connection = (p > 0.5)
            a0 += (v.x > 0.5f);
            a1 += (v.y > 0.5f);
            a2 += (v.z > 0.5f);
            a3 += (v.w > 0.5f);
        }
        atomicAdd(&g_overlap[col + 0], a0);
        atomicAdd(&g_overlap[col + 1], a1);
        atomicAdd(&g_overlap[col + 2], a2);
        atomicAdd(&g_overlap[col + 3], a3);
    }

    // ---- tile completion ----
    __threadfence();
    __syncthreads();
    if (t == 0) s_last = atomicAdd(&g_tilecnt[blockIdx.x], 1);
    __syncthreads();
    if (s_last != NSPLITS - 1) return;   // 36 of 37 blocks per tile exit here

    // ---- phase 2: histogram own finalized overlaps ----
    __threadfence();   // acquire: peer blocks' overlap atomics visible
    const int4 ov = *reinterpret_cast<const int4*>(&g_overlap[col]);
    atomicAdd(&g_hist[ov.x], 1);
    atomicAdd(&g_hist[ov.y], 1);
    atomicAdd(&g_hist[ov.z], 1);
    atomicAdd(&g_hist[ov.w], 1);

    // global barrier among the 16 surviving blocks
    __threadfence();
    __syncthreads();
    if (t == 0) {
        atomicAdd(&g_histdone, 1);
        while (atomicAdd(&g_histdone, 0) < NTILES) __nanosleep(100);
    }
    __syncthreads();
    __threadfence();   // acquire: all tiles' hist atomics visible

    // ---- phase 3a: redundant findT (36 bins/thread, shfl block scan) ----
    int v[36];
    {
        const int4* h4 = reinterpret_cast<const int4*>(g_hist);
        int b = t * 9;
        #pragma unroll
        for (int q = 0; q < 9; q++) {
            int4 hv = h4[b + q];
            v[q * 4 + 0] = hv.x; v[q * 4 + 1] = hv.y;
            v[q * 4 + 2] = hv.z; v[q * 4 + 3] = hv.w;
        }
    }
    int lsum = 0;
    #pragma unroll
    for (int j = 0; j < 36; j++) lsum += v[j];

    int incl = lsum;
    #pragma unroll
    for (int o = 1; o < 32; o <<= 1) {
        int s = __shfl_up_sync(0xffffffffu, incl, o);
        if (lane >= o) incl += s;
    }
    if (lane == 31) warp_sums[w] = incl;
    __syncthreads();
    if (w == 0 && lane < 8) {
        int ws = warp_sums[lane];
        int wincl = ws;
        #pragma unroll
        for (int o = 1; o < 8; o <<= 1) {
            int s = __shfl_up_sync(0x000000ffu, wincl, o);
            if (lane >= o) wincl += s;
        }
        warp_sums[lane] = wincl - ws;
    }
    __syncthreads();
    int run = incl - lsum + warp_sums[w];   // exclusive prefix

    {
        int b0 = t * 36;
        #pragma unroll
        for (int j = 0; j < 36; j++) {
            int h = v[j];
            if (run <= CUT && run + h > CUT) {
                sT   = b0 + j;
                sNat = TOPK - (OUT_DIM - (run + h));  // ties to take
            }
            run += h;
        }
    }
    __syncthreads();
    const int T = sT;
    const int nat = sNat;

    // ---- phase 3b: write output slice, restore overlap, collect ties ----
    *reinterpret_cast<int4*>(&g_overlap[col]) = make_int4(0, 0, 0, 0);
    float4 f;
    f.x = (ov.x > T) ? 1.0f : 0.0f;
    f.y = (ov.y > T) ? 1.0f : 0.0f;
    f.z = (ov.z > T) ? 1.0f : 0.0f;
    f.w = (ov.w > T) ? 1.0f : 0.0f;
    *reinterpret_cast<float4*>(out + col) = f;
    if (ov.x == T) { int q = atomicAdd(&g_ntie, 1); g_tie[q] = col + 0; }
    if (ov.y == T) { int q = atomicAdd(&g_ntie, 1); g_tie[q] = col + 1; }
    if (ov.z == T) { int q = atomicAdd(&g_ntie, 1); g_tie[q] = col + 2; }
    if (ov.w == T) { int q = atomicAdd(&g_ntie, 1); g_tie[q] = col + 3; }

    // ---- phase 4: globally last block resolves ties + restores scratch ----
    __threadfence();
    __syncthreads();
    if (t == 0) s_last = atomicAdd(&g_donecnt, 1);
    __syncthreads();
    if (s_last == NTILES - 1) {
        __threadfence();   // acquire: all blocks' g_tie writes visible
        int n = atomicAdd(&g_ntie, 0);
        for (int k = t; k < n; k += 256) {
            int idx = g_tie[k];
            int rank = 0;
            for (int j = 0; j < n; j++) rank += (g_tie[j] < idx);
            if (rank < nat) out[idx] = 1.0f;
        }
        // restore for next graph replay (loader guarantees zeros on call 0)
        int4* h4 = reinterpret_cast<int4*>(g_hist);
        for (int q = t; q < NBINS / 4; q += 256)
            h4[q] = make_int4(0, 0, 0, 0);
        if (t < NTILES) g_tilecnt[t] = 0;
        if (t == 0) { g_histdone = 0; g_donecnt = 0; g_ntie = 0; }
    }
}

// ---------------- launch ----------------
extern "C" void kernel_launch(void* const* d_in, const int* in_sizes, int n_in,
                              void* d_out, int out_size) {
    const int*   x;
    const float* p;
    if (in_sizes[0] == IN_DIM) {
        x = (const int*)d_in[0];
        p = (const float*)d_in[1];
    } else {
        x = (const int*)d_in[1];
        p = (const float*)d_in[0];
    }

    k_fused<<<dim3(NTILES, NSPLITS), 256>>>(p, x, (float*)d_out);
}